// round 7
// baseline (speedup 1.0000x reference)
#include <cuda_runtime.h>
#include <cuda_fp16.h>
#include <cstdint>
#include <cstring>
#include <math.h>

#define BSZ   16
#define TSEQ  2048
#define DIM   1024
#define MDIM  128
#define HID   512
#define WIN   16
#define HALF  8
#define MAXP  6
#define NW    128
#define PPAIR 768
#define KSEL  614
#define TKEEP 1434
#define NTOK  (BSZ*TSEQ)
#define NCOL  640
#define LN_EPS 1e-5f

#define KC        32                  // K chunk
#define NKCHUNK   (DIM/KC)            // 32
#define NSTAGE    3
#define SSTRIDE   40                  // padded half stride per row (32 used)
#define A_PL_B    (128*SSTRIDE*2)     // 10240 bytes
#define B_PL_B    (64*SSTRIDE*2)      // 5120 bytes
#define OFF_AL    A_PL_B
#define OFF_BH    (2*A_PL_B)
#define OFF_BL    (2*A_PL_B + B_PL_B)
#define STAGE_B   (2*A_PL_B + 2*B_PL_B)   // 30720
#define GEMM_SMEM (NSTAGE*STAGE_B)        // 92160
#define NIMP      8                   // imp N-tiles (bx = 2..9)

// ---------------- scratch ---------------------------------------------------
__device__ __half g_Ah[(size_t)NTOK*DIM];
__device__ __half g_Al[(size_t)NTOK*DIM];
__device__ __half g_Wh[NCOL*DIM];         // folded weights hi, [n][k]
__device__ __half g_Wl[NCOL*DIM];         // folded weights (lo*2048), [n][k]
__device__ float g_cvec[NCOL];
__device__ float g_mraw[(size_t)NTOK*MDIM];
__device__ float g_impPart[NIMP*NTOK];
__device__ float g_imp[NTOK];
__device__ int   g_pi[BSZ*PPAIR];
__device__ int   g_pj[BSZ*PPAIR];
__device__ float g_ps[BSZ*PPAIR];
__device__ float g_pal[BSZ*PPAIR];
__device__ int   g_drop[BSZ*TSEQ];
__device__ int   g_pos[BSZ*TSEQ];
__device__ int   g_partner[BSZ*TSEQ];
__device__ float g_atok[BSZ*TSEQ];

// ---------------- helpers ---------------------------------------------------
__device__ __forceinline__ float block_reduce_sum(float v, float* sbuf) {
    int lane = threadIdx.x & 31, wid = threadIdx.x >> 5;
    #pragma unroll
    for (int o = 16; o; o >>= 1) v += __shfl_xor_sync(0xffffffffu, v, o);
    if (lane == 0) sbuf[wid] = v;
    __syncthreads();
    int nw = blockDim.x >> 5;
    float r = (threadIdx.x < nw) ? sbuf[threadIdx.x] : 0.f;
    if (wid == 0) {
        #pragma unroll
        for (int o = 16; o; o >>= 1) r += __shfl_xor_sync(0xffffffffu, r, o);
        if (lane == 0) sbuf[0] = r;
    }
    __syncthreads();
    r = sbuf[0];
    __syncthreads();
    return r;
}

__device__ __forceinline__ void mma16816(float c[4], const unsigned a[4], const unsigned b[2]) {
    asm volatile("mma.sync.aligned.m16n8k16.row.col.f32.f16.f16.f32 "
        "{%0,%1,%2,%3}, {%4,%5,%6,%7}, {%8,%9}, {%0,%1,%2,%3};"
        : "+f"(c[0]), "+f"(c[1]), "+f"(c[2]), "+f"(c[3])
        : "r"(a[0]), "r"(a[1]), "r"(a[2]), "r"(a[3]), "r"(b[0]), "r"(b[1]));
}

__device__ __forceinline__ void ldsm_x4(unsigned r[4], unsigned addr) {
    asm volatile("ldmatrix.sync.aligned.m8n8.x4.shared.b16 {%0,%1,%2,%3}, [%4];"
        : "=r"(r[0]), "=r"(r[1]), "=r"(r[2]), "=r"(r[3]) : "r"(addr));
}

__device__ __forceinline__ unsigned smem_u32(const void* p) {
    unsigned a;
    asm("{ .reg .u64 t; cvta.to.shared.u64 t, %1; cvt.u32.u64 %0, t; }" : "=r"(a) : "l"(p));
    return a;
}

__device__ __forceinline__ void cp16(unsigned dst, const void* src) {
    asm volatile("cp.async.cg.shared.global [%0], [%1], 16;" :: "r"(dst), "l"(src));
}
#define CP_COMMIT() asm volatile("cp.async.commit_group;" ::: "memory")
#define CP_WAIT(N)  asm volatile("cp.async.wait_group %0;" :: "n"(N) : "memory")

__device__ __forceinline__ unsigned pack_h2(__half a, __half b) {
    __half2 h = __halves2half2(a, b);
    unsigned u; memcpy(&u, &h, 4); return u;
}

// ---------------- K0: LN + split to fp16 hi/lo ------------------------------
__global__ void ln_split_kernel(const float* __restrict__ x) {
    int t = blockIdx.x;
    __shared__ float sbuf[32];
    const float4* row = (const float4*)(x + (size_t)t * DIM);
    float4 v = row[threadIdx.x];
    float s = v.x + v.y + v.z + v.w;
    float tot = block_reduce_sum(s, sbuf);
    float mean = tot * (1.0f / DIM);
    float d0 = v.x - mean, d1 = v.y - mean, d2 = v.z - mean, d3 = v.w - mean;
    float ss = d0*d0 + d1*d1 + d2*d2 + d3*d3;
    float vtot = block_reduce_sum(ss, sbuf);
    float rs = rsqrtf(vtot * (1.0f / DIM) + LN_EPS);
    float f[4] = {d0*rs, d1*rs, d2*rs, d3*rs};
    unsigned hp[2], lp[2];
    #pragma unroll
    for (int e = 0; e < 2; e++) {
        __half h0 = __float2half_rn(f[2*e]),   h1 = __float2half_rn(f[2*e+1]);
        __half l0 = __float2half_rn((f[2*e]   - __half2float(h0)) * 2048.f);
        __half l1 = __float2half_rn((f[2*e+1] - __half2float(h1)) * 2048.f);
        hp[e] = pack_h2(h0, h1);  lp[e] = pack_h2(l0, l1);
    }
    size_t off = (size_t)t * DIM + threadIdx.x * 4;
    *(uint2*)(g_Ah + off) = make_uint2(hp[0], hp[1]);
    *(uint2*)(g_Al + off) = make_uint2(lp[0], lp[1]);
}

// ---------------- fold weights into split fp16 [n][k] -----------------------
__global__ void foldW_kernel(const float* __restrict__ wm, const float* __restrict__ w1,
                             const float* __restrict__ gm, const float* __restrict__ gi) {
    __shared__ float tile[32][33];
    int k0 = blockIdx.x * 32, n0 = blockIdx.y * 32;
    int tx = threadIdx.x, ty = threadIdx.y;
    #pragma unroll
    for (int j = 0; j < 4; j++) {
        int k = k0 + ty + j*8, n = n0 + tx;
        float w = (n < MDIM) ? gm[k] * wm[k*MDIM + n]
                             : gi[k] * w1[k*HID + (n - MDIM)];
        tile[ty + j*8][tx] = w;
    }
    __syncthreads();
    #pragma unroll
    for (int j = 0; j < 4; j++) {
        int n = n0 + ty + j*8, k = k0 + tx;
        float w = tile[tx][ty + j*8];
        __half h = __float2half_rn(w);
        g_Wh[(size_t)n*DIM + k] = h;
        g_Wl[(size_t)n*DIM + k] = __float2half_rn((w - __half2float(h)) * 2048.f);
    }
}

__global__ void foldC_kernel(const float* __restrict__ wm, const float* __restrict__ w1,
                             const float* __restrict__ bm, const float* __restrict__ bi,
                             const float* __restrict__ b1) {
    int n = blockIdx.x;
    __shared__ float sbuf[32];
    float s = 0.f;
    if (n < MDIM) {
        for (int d = threadIdx.x; d < DIM; d += blockDim.x) s += bm[d] * wm[d*MDIM + n];
    } else {
        for (int d = threadIdx.x; d < DIM; d += blockDim.x) s += bi[d] * w1[d*HID + (n - MDIM)];
    }
    float tot = block_reduce_sum(s, sbuf);
    if (threadIdx.x == 0) g_cvec[n] = tot + ((n >= MDIM) ? b1[n - MDIM] : 0.f);
}

// ---------------- K1: split-fp16 HMMA GEMM, 128x64 tile, 2 CTAs/SM ----------
// grid (10, 256): bn = 64*bx, bm = 128*by.  256 threads = 4x2 warps, 32x32/warp.
__global__ __launch_bounds__(256, 2)
void gemm_hmma_kernel(const float* __restrict__ w2) {
    extern __shared__ __half sh[];
    const unsigned shs = smem_u32(sh);
    const int tid  = threadIdx.x;
    const int warp = tid >> 5, lane = tid & 31;
    const int gid  = lane >> 2, t4 = lane & 3;
    const int bx = blockIdx.x;
    const int bn = bx * 64, bm = blockIdx.y * 128;
    const int wm = (warp >> 1) * 32, wn = (warp & 1) * 32;

    // cp.async slices
    const int arow = tid >> 1, akoff = (tid & 1) * 16;
    const int brow = tid >> 2, bkoff = (tid & 3) * 8;
    const __half* srcAh = g_Ah + (size_t)(bm + arow) * DIM + akoff;
    const __half* srcAl = g_Al + (size_t)(bm + arow) * DIM + akoff;
    const __half* srcBh = g_Wh + (size_t)(bn + brow) * DIM + bkoff;
    const __half* srcBl = g_Wl + (size_t)(bn + brow) * DIM + bkoff;
    const unsigned dA = (unsigned)(arow * SSTRIDE + akoff) * 2u;
    const unsigned dB = (unsigned)(brow * SSTRIDE + bkoff) * 2u;

    // ldmatrix lane address components
    const int a_row = lane & 15;
    const int a_koff = (lane >> 4) * 8;
    const int b_row = (lane & 7) + ((lane >> 4) << 3);
    const int b_koff = ((lane >> 3) & 1) * 8;

    float acc0[2][4][4], acc1[2][4][4];
    #pragma unroll
    for (int i = 0; i < 2; i++)
        #pragma unroll
        for (int j = 0; j < 4; j++)
            #pragma unroll
            for (int e = 0; e < 4; e++) { acc0[i][j][e] = 0.f; acc1[i][j][e] = 0.f; }

    // ---- prologue: fill stages 0..NSTAGE-2 ----
    #pragma unroll
    for (int cc = 0; cc < NSTAGE-1; cc++) {
        unsigned sb = shs + (unsigned)(cc * STAGE_B);
        cp16(sb + dA,               srcAh + cc*KC);
        cp16(sb + dA + 16,          srcAh + cc*KC + 8);
        cp16(sb + OFF_AL + dA,      srcAl + cc*KC);
        cp16(sb + OFF_AL + dA + 16, srcAl + cc*KC + 8);
        cp16(sb + OFF_BH + dB,      srcBh + cc*KC);
        cp16(sb + OFF_BL + dB,      srcBl + cc*KC);
        CP_COMMIT();
    }

    int s_cur = 0, s_fill = NSTAGE - 1;
    for (int c = 0; c < NKCHUNK; c++) {
        if (c + 1 < NKCHUNK) CP_WAIT(1); else CP_WAIT(0);
        __syncthreads();

        // ---- compute on stage s_cur ----
        {
            const unsigned stA = shs + (unsigned)(s_cur * STAGE_B);
            #pragma unroll
            for (int ks = 0; ks < 2; ks++) {
                const int kb = ks*16;
                unsigned ah[2][4], al[2][4], bh[2][4], bl[2][4];
                #pragma unroll
                for (int ma = 0; ma < 2; ma++) {
                    unsigned adr = stA + (unsigned)((wm + ma*16 + a_row)*SSTRIDE + kb + a_koff)*2u;
                    ldsm_x4(ah[ma], adr);
                    ldsm_x4(al[ma], adr + (unsigned)OFF_AL);
                }
                #pragma unroll
                for (int g = 0; g < 2; g++) {
                    unsigned bdr = stA + (unsigned)OFF_BH
                                 + (unsigned)((wn + g*16 + b_row)*SSTRIDE + kb + b_koff)*2u;
                    ldsm_x4(bh[g], bdr);
                    ldsm_x4(bl[g], bdr + (unsigned)(OFF_BL - OFF_BH));
                }
                #pragma unroll
                for (int ma = 0; ma < 2; ma++)
                    #pragma unroll
                    for (int nb = 0; nb < 4; nb++) {
                        const unsigned* bhf = &bh[nb>>1][(nb&1)*2];
                        const unsigned* blf = &bl[nb>>1][(nb&1)*2];
                        mma16816(acc0[ma][nb], ah[ma], bhf);
                        mma16816(acc1[ma][nb], ah[ma], blf);
                        mma16816(acc1[ma][nb], al[ma], bhf);
                    }
            }
        }
        // ---- fill stage s_fill with chunk c+NSTAGE-1 ----
        int cc = c + NSTAGE - 1;
        if (cc < NKCHUNK) {
            unsigned sb = shs + (unsigned)(s_fill * STAGE_B);
            cp16(sb + dA,               srcAh + cc*KC);
            cp16(sb + dA + 16,          srcAh + cc*KC + 8);
            cp16(sb + OFF_AL + dA,      srcAl + cc*KC);
            cp16(sb + OFF_AL + dA + 16, srcAl + cc*KC + 8);
            cp16(sb + OFF_BH + dB,      srcBh + cc*KC);
            cp16(sb + OFF_BL + dB,      srcBl + cc*KC);
            CP_COMMIT();
        }
        if (++s_cur == NSTAGE) s_cur = 0;
        if (++s_fill == NSTAGE) s_fill = 0;
    }
    __syncthreads();

    // ---- fused epilogue ----
    const float inv = 1.f / 2048.f;
    if (bx < 2) {
        // match head: write raw fp32 features (normalized later in match_kernel)
        #pragma unroll
        for (int ma = 0; ma < 2; ma++) {
            int r0 = bm + wm + ma*16 + gid;
            #pragma unroll
            for (int nb = 0; nb < 4; nb++) {
                int c0 = bn + wn + nb*8 + 2*t4;    // 0..127
                float cv0 = g_cvec[c0], cv1 = g_cvec[c0+1];
                float2 lo = make_float2(acc0[ma][nb][0] + acc1[ma][nb][0]*inv + cv0,
                                        acc0[ma][nb][1] + acc1[ma][nb][1]*inv + cv1);
                float2 hi = make_float2(acc0[ma][nb][2] + acc1[ma][nb][2]*inv + cv0,
                                        acc0[ma][nb][3] + acc1[ma][nb][3]*inv + cv1);
                *(float2*)&g_mraw[(size_t)r0*MDIM + c0]     = lo;
                *(float2*)&g_mraw[(size_t)(r0+8)*MDIM + c0] = hi;
            }
        }
    } else {
        // imp head: per-row partial sum of relu(v)*w2 over this 64-col tile
        float sp[4] = {0.f, 0.f, 0.f, 0.f};
        #pragma unroll
        for (int ma = 0; ma < 2; ma++) {
            #pragma unroll
            for (int nb = 0; nb < 4; nb++) {
                int c0 = wn + nb*8 + 2*t4;          // 0..63 within tile
                int gc = bn + c0;                    // global col in [128, 640)
                float cv0 = g_cvec[gc], cv1 = g_cvec[gc + 1];
                float w20 = w2[gc - MDIM], w21 = w2[gc - MDIM + 1];
                float v00 = acc0[ma][nb][0] + acc1[ma][nb][0]*inv + cv0;
                float v01 = acc0[ma][nb][1] + acc1[ma][nb][1]*inv + cv1;
                float v10 = acc0[ma][nb][2] + acc1[ma][nb][2]*inv + cv0;
                float v11 = acc0[ma][nb][3] + acc1[ma][nb][3]*inv + cv1;
                sp[2*ma]   += fmaxf(v00, 0.f)*w20 + fmaxf(v01, 0.f)*w21;
                sp[2*ma+1] += fmaxf(v10, 0.f)*w20 + fmaxf(v11, 0.f)*w21;
            }
        }
        #pragma unroll
        for (int s = 0; s < 4; s++) {
            sp[s] += __shfl_xor_sync(0xffffffffu, sp[s], 1);
            sp[s] += __shfl_xor_sync(0xffffffffu, sp[s], 2);
        }
        float* red = (float*)sh;                    // [2 wn][128 rows]
        if (t4 == 0) {
            int wncol = warp & 1;
            red[wncol*128 + wm + gid]          = sp[0];
            red[wncol*128 + wm + gid + 8]      = sp[1];
            red[wncol*128 + wm + 16 + gid]     = sp[2];
            red[wncol*128 + wm + 16 + gid + 8] = sp[3];
        }
        __syncthreads();
        if (tid < 128)
            g_impPart[(size_t)(bx - 2)*NTOK + bm + tid] = red[tid] + red[128 + tid];
    }
}

// ---------------- K2': sum partials + sigmoid -------------------------------
__global__ void sigmoid_kernel(const float* __restrict__ b2) {
    int t = blockIdx.x * 256 + threadIdx.x;
    float s = b2[0];
    #pragma unroll
    for (int p = 0; p < NIMP; p++) s += g_impPart[(size_t)p*NTOK + t];
    g_imp[t] = 1.f / (1.f + expf(-s));
}

// ---------------- K3: per-window sim + greedy matching ---------------------
__global__ void match_kernel() {
    __shared__ float sm[4][WIN*MDIM];
    __shared__ float snorm[4][WIN];
    int wslot = threadIdx.x >> 5;
    int warp = blockIdx.x * 4 + wslot;
    int lane = threadIdx.x & 31;
    int b = warp / NW, w = warp % NW;
    int base_t = b * TSEQ + w * WIN;
    float* mwin = sm[wslot];
    float* nrm  = snorm[wslot];

    const float4* src = (const float4*)(g_mraw + (size_t)base_t * MDIM);
    #pragma unroll
    for (int j = 0; j < 16; j++) {
        int i = lane + 32*j;                      // row j of the window
        float4 v = src[i];
        ((float4*)mwin)[i] = v;
        float sq = v.x*v.x + v.y*v.y + v.z*v.z + v.w*v.w;
        #pragma unroll
        for (int o = 16; o; o >>= 1) sq += __shfl_xor_sync(0xffffffffu, sq, o);
        if (lane == 0) nrm[j] = sqrtf(sq);
    }
    __syncwarp();

    float sv[2];
    #pragma unroll
    for (int q = 0; q < 2; q++) {
        int f = lane + q*32;
        int a = f >> 3, c = f & 7;
        const float* va = mwin + (2*a) * MDIM;
        const float* vb = mwin + (2*c + 1) * MDIM;
        float acc = 0.f;
        #pragma unroll 8
        for (int d = 0; d < MDIM; d++) acc += va[d] * vb[d];
        acc = acc / (nrm[2*a] * nrm[2*c + 1]);
        sv[q] = (acc < -10.0f) ? -INFINITY : acc;
    }

    unsigned rowAvail = 0xFF, colAvail = 0xFF;
    int myA = 0, myC = 0; float myV = 0.f;
    #pragma unroll
    for (int r = 0; r < MAXP; r++) {
        float bestv = -INFINITY; int besti = 9999;
        #pragma unroll
        for (int q = 0; q < 2; q++) {
            int f = lane + q*32;
            int a = f >> 3, c = f & 7;
            bool av = ((rowAvail >> a) & 1) && ((colAvail >> c) & 1);
            float v = av ? sv[q] : -INFINITY;
            int   idx = av ? f : 9999;
            if (v > bestv || (v == bestv && idx < besti)) { bestv = v; besti = idx; }
        }
        #pragma unroll
        for (int o = 16; o; o >>= 1) {
            float ov = __shfl_xor_sync(0xffffffffu, bestv, o);
            int   oi = __shfl_xor_sync(0xffffffffu, besti, o);
            if (ov > bestv || (ov == bestv && oi < besti)) { bestv = ov; besti = oi; }
        }
        int a = besti >> 3, c = besti & 7;
        rowAvail &= ~(1u << a);
        colAvail &= ~(1u << c);
        if (lane == r) { myA = a; myC = c; myV = bestv; }
    }

    if (lane < MAXP) {
        int i_loc = w*WIN + 2*myA;
        int j_loc = w*WIN + 2*myC + 1;
        float ii = g_imp[b*TSEQ + i_loc];
        float ij = g_imp[b*TSEQ + j_loc];
        int p = b*PPAIR + w*MAXP + lane;
        g_pi[p] = i_loc;
        g_pj[p] = j_loc;
        g_ps[p] = myV - 0.25f * (ii + ij);
        g_pal[p] = 1.f / (1.f + expf(-5.f * (ii - ij)));
    }
}

// ---------------- K4: per-batch top-K, scatter, prefix-scan ----------------
__global__ void select_pack_kernel() {
    int b = blockIdx.x;
    int tid = threadIdx.x;
    __shared__ float svv[1024];
    __shared__ int   sii[1024];
    __shared__ int   sdrop[TSEQ];
    __shared__ int   sc[1024];

    svv[tid] = (tid < PPAIR) ? g_ps[b*PPAIR + tid] : -INFINITY;
    sii[tid] = tid;
    __syncthreads();

    for (int ksz = 2; ksz <= 1024; ksz <<= 1) {
        for (int jsz = ksz >> 1; jsz > 0; jsz >>= 1) {
            int ixj = tid ^ jsz;
            if (ixj > tid) {
                float v1 = svv[tid], v2 = svv[ixj];
                int   i1 = sii[tid], i2 = sii[ixj];
                bool tid_before = (v1 > v2) || (v1 == v2 && i1 < i2);
                bool doswap = ((tid & ksz) == 0) ? !tid_before : tid_before;
                if (doswap) { svv[tid]=v2; svv[ixj]=v1; sii[tid]=i2; sii[ixj]=i1; }
            }
            __syncthreads();
        }
    }

    for (int t = tid; t < TSEQ; t += 1024) { sdrop[t] = 0; g_partner[b*TSEQ + t] = -1; }
    __syncthreads();

    if (tid < KSEL) {
        int p = sii[tid];
        int i = g_pi[b*PPAIR + p];
        int j = g_pj[b*PPAIR + p];
        sdrop[j] = 1;
        g_partner[b*TSEQ + i] = j;
        g_atok[b*TSEQ + i] = g_pal[b*PPAIR + p];
    }
    __syncthreads();

    int k0 = 1 - sdrop[2*tid];
    int k1 = 1 - sdrop[2*tid + 1];
    int mysum = k0 + k1;
    sc[tid] = mysum;
    __syncthreads();
    for (int off = 1; off < 1024; off <<= 1) {
        int add = (tid >= off) ? sc[tid - off] : 0;
        __syncthreads();
        sc[tid] += add;
        __syncthreads();
    }
    int excl = sc[tid] - mysum;
    g_pos[b*TSEQ + 2*tid]     = excl;
    g_pos[b*TSEQ + 2*tid + 1] = excl + k0;
    g_drop[b*TSEQ + 2*tid]     = sdrop[2*tid];
    g_drop[b*TSEQ + 2*tid + 1] = sdrop[2*tid + 1];
}

// ---------------- K5: merge + compact output -------------------------------
__global__ void pack_out_kernel(const float* __restrict__ x, float* __restrict__ out) {
    int t = blockIdx.x, b = blockIdx.y;
    int bt = b*TSEQ + t;
    if (g_drop[bt]) return;
    int r = g_pos[bt];
    const float4* xi = (const float4*)(x + (size_t)bt * DIM);
    float4* o = (float4*)(out + ((size_t)b*TKEEP + r) * DIM);
    int pj = g_partner[bt];
    if (pj < 0) {
        for (int i = threadIdx.x; i < DIM/4; i += blockDim.x) o[i] = xi[i];
    } else {
        float a  = g_atok[bt];
        float ai = a, aj = 1.f - a;
        const float4* xj = (const float4*)(x + ((size_t)b*TSEQ + pj) * DIM);
        for (int i = threadIdx.x; i < DIM/4; i += blockDim.x) {
            float4 u = xi[i], v = xj[i], m, w;
            m.x = ai*u.x + aj*v.x;  m.y = ai*u.y + aj*v.y;
            m.z = ai*u.z + aj*v.z;  m.w = ai*u.w + aj*v.w;
            w.x = u.x + (m.x - u.x); w.y = u.y + (m.y - u.y);
            w.z = u.z + (m.z - u.z); w.w = u.w + (m.w - u.w);
            o[i] = w;
        }
    }
}

// ---------------- launch ----------------------------------------------------
extern "C" void kernel_launch(void* const* d_in, const int* in_sizes, int n_in,
                              void* d_out, int out_size) {
    const float* x    = (const float*)d_in[0];
    const float* gm   = (const float*)d_in[1];
    const float* bm   = (const float*)d_in[2];
    const float* wm   = (const float*)d_in[3];
    const float* gi   = (const float*)d_in[4];
    const float* bi   = (const float*)d_in[5];
    const float* w1   = (const float*)d_in[6];
    const float* b1   = (const float*)d_in[7];
    const float* w2   = (const float*)d_in[8];
    const float* b2   = (const float*)d_in[9];
    float* out = (float*)d_out;

    cudaFuncSetAttribute(gemm_hmma_kernel, cudaFuncAttributeMaxDynamicSharedMemorySize, GEMM_SMEM);

    ln_split_kernel<<<NTOK, 256>>>(x);
    foldW_kernel<<<dim3(DIM/32, NCOL/32), dim3(32, 8)>>>(wm, w1, gm, gi);
    foldC_kernel<<<NCOL, 256>>>(wm, w1, bm, bi, b1);
    gemm_hmma_kernel<<<dim3(NCOL/64, NTOK/128), 256, GEMM_SMEM>>>(w2);
    sigmoid_kernel<<<NTOK/256, 256>>>(b2);
    match_kernel<<<(BSZ*NW)/4, 128>>>();
    select_pack_kernel<<<BSZ, 1024>>>();
    pack_out_kernel<<<dim3(TSEQ, BSZ), 128>>>(x, out);
}